// round 3
// baseline (speedup 1.0000x reference)
#include <cuda_runtime.h>

#define B_  8
#define T_  12
#define P_  1000
#define N_  20000
#define E_  60000
#define FP_ 32
#define FN_ 32
#define H_  12
#define KD  768   // IN_DIM = HID = (FP+FN)*T

// ---------------- device scratch (no allocations allowed) ----------------
__device__ int   g_cnt[N_];
__device__ int   g_cursor[N_];
__device__ int   g_offs[N_ + 1];
__device__ int   g_edge[E_];
__device__ float g_mlp[(size_t)B_ * N_ * KD];   // 160000 x 768 fp32 (491.5 MB)

// ---------------- CSR build: node -> list of patch indices ----------------
__global__ void k_init() {
    int i = blockIdx.x * blockDim.x + threadIdx.x;
    if (i < N_) g_cnt[i] = 0;
}

__global__ void k_count(const int* __restrict__ mapper) {
    int e = blockIdx.x * blockDim.x + threadIdx.x;
    if (e < E_) atomicAdd(&g_cnt[mapper[e]], 1);
}

// exclusive scan of g_cnt (N=20000) with one 1024-thread block; also zeroes cursor
__global__ void k_scan() {
    __shared__ int wsum[32];
    const int per = 20;
    int tid  = threadIdx.x;
    int base = tid * per;
    int loc[20];
    int s = 0;
#pragma unroll
    for (int i = 0; i < per; i++) {
        int idx = base + i;
        int v = (idx < N_) ? g_cnt[idx] : 0;
        loc[i] = s;
        s += v;
    }
    int lane = tid & 31, w = tid >> 5;
    int inc = s;
#pragma unroll
    for (int o = 1; o < 32; o <<= 1) {
        int t = __shfl_up_sync(0xffffffffu, inc, o);
        if (lane >= o) inc += t;
    }
    if (lane == 31) wsum[w] = inc;
    __syncthreads();
    if (w == 0) {
        int v = wsum[lane], vi = v;
#pragma unroll
        for (int o = 1; o < 32; o <<= 1) {
            int t = __shfl_up_sync(0xffffffffu, vi, o);
            if (lane >= o) vi += t;
        }
        wsum[lane] = vi - v;   // exclusive warp prefix
    }
    __syncthreads();
    int tbase = wsum[w] + (inc - s);
#pragma unroll
    for (int i = 0; i < per; i++) {
        int idx = base + i;
        if (idx <= N_) g_offs[idx] = tbase + loc[i];
    }
    for (int i = tid; i < N_; i += blockDim.x) g_cursor[i] = 0;
}

__global__ void k_fill(const int* __restrict__ mapper, const int* __restrict__ batch) {
    int e = blockIdx.x * blockDim.x + threadIdx.x;
    if (e < E_) {
        int node = mapper[e];
        int pos  = atomicAdd(&g_cursor[node], 1);
        g_edge[g_offs[node] + pos] = batch[e];
    }
}

// ------- build mlp_in: [nx transpose | segment-mean of gathered patch_x] -------
// one warp per (n, b): lane -> (tq = lane/8 in 0..3, fq = 4*(lane%8));
// each lane owns t in {tq, tq+4, tq+8}, 4 floats each.
__global__ void __launch_bounds__(256) k_build(const float* __restrict__ patch_x,
                                               const float* __restrict__ nodes_x) {
    int gw = blockIdx.x * 8 + (threadIdx.x >> 5);
    if (gw >= N_ * B_) return;
    int n = gw >> 3;
    int b = gw & 7;
    int lane = threadIdx.x & 31;
    int fq = (lane & 7) * 4;
    int tq = lane >> 3;

    float* dst = g_mlp + (size_t)(b * N_ + n) * KD;

    // first half: nodes_x (B,T,N,FN) -> cols t*32+f
#pragma unroll
    for (int j = 0; j < 3; j++) {
        int t = tq + 4 * j;
        float4 v = __ldg((const float4*)(nodes_x + ((size_t)(b * T_ + t) * N_ + n) * FN_ + fq));
        *(float4*)(dst + t * FN_ + fq) = v;
    }

    // second half: mean over this node's patches of patch_x (B,T,P,FP)
    int o0 = g_offs[n], o1 = g_offs[n + 1];
    float4 a0 = make_float4(0.f, 0.f, 0.f, 0.f), a1 = a0, a2 = a0;
    for (int e = o0; e < o1; e++) {
        int p = __ldg(&g_edge[e]);
        float4 v0 = __ldg((const float4*)(patch_x + ((size_t)(b * T_ + tq)     * P_ + p) * FP_ + fq));
        float4 v1 = __ldg((const float4*)(patch_x + ((size_t)(b * T_ + tq + 4) * P_ + p) * FP_ + fq));
        float4 v2 = __ldg((const float4*)(patch_x + ((size_t)(b * T_ + tq + 8) * P_ + p) * FP_ + fq));
        a0.x += v0.x; a0.y += v0.y; a0.z += v0.z; a0.w += v0.w;
        a1.x += v1.x; a1.y += v1.y; a1.z += v1.z; a1.w += v1.w;
        a2.x += v2.x; a2.y += v2.y; a2.z += v2.z; a2.w += v2.w;
    }
    int deg = o1 - o0;
    float inv = 1.0f / (float)(deg > 1 ? deg : 1);
    a0.x *= inv; a0.y *= inv; a0.z *= inv; a0.w *= inv;
    a1.x *= inv; a1.y *= inv; a1.z *= inv; a1.w *= inv;
    a2.x *= inv; a2.y *= inv; a2.z *= inv; a2.w *= inv;
    *(float4*)(dst + T_ * FN_ + tq * FP_ + fq)        = a0;
    *(float4*)(dst + T_ * FN_ + (tq + 4) * FP_ + fq)  = a1;
    *(float4*)(dst + T_ * FN_ + (tq + 8) * FP_ + fq)  = a2;
}

// ------------- fused GEMM: out = relu(mlp_in @ W1 + b1) @ W2 + b2 -------------
// block = 256 threads, 64-row tile. A (64x768) fully in smem.
// hidden processed in 6 chunks of 128; per-thread 4x8 microtile via fma.rn.f32x2.
#define SMEM_BYTES ((64 * KD + 16 * 128 + KD) * 4)

__global__ void __launch_bounds__(256, 1) k_gemm(const float* __restrict__ W1,
                                                 const float* __restrict__ b1,
                                                 const float* __restrict__ W2,
                                                 const float* __restrict__ b2,
                                                 float* __restrict__ out) {
    extern __shared__ float sm[];
    float* As  = sm;                  // [64][768]
    float* Bs  = sm + 64 * KD;        // [16][128]
    float* b1s = Bs + 16 * 128;       // [768]

    int tid = threadIdx.x;
    size_t r0 = (size_t)blockIdx.x * 64;
    const float* Ag = g_mlp + r0 * KD;

    // load A tile: warp = one row, 32 consecutive float4 (coalesced, conflict-free store)
#pragma unroll
    for (int it = 0; it < 48; it++) {
        int idx = it * 256 + tid;          // 0..12287
        int row = idx / 192;
        int kq  = idx - row * 192;
        float4 v = *(const float4*)(Ag + (size_t)row * KD + kq * 4);
        *(float4*)(As + row * KD + kq * 4) = v;
    }
    for (int i = tid; i < KD; i += 256) b1s[i] = b1[i];

    int rg = tid >> 4;   // 0..15: 4-row group
    int cg = tid & 15;   // 0..15: 8-col group

    float pacc[4][12];
#pragma unroll
    for (int i = 0; i < 4; i++)
#pragma unroll
        for (int hh = 0; hh < 12; hh++) pacc[i][hh] = 0.f;

#pragma unroll 1
    for (int jc = 0; jc < 6; jc++) {
        unsigned long long acc[4][4];   // 4 rows x 4 col-pairs (f32x2)
#pragma unroll
        for (int i = 0; i < 4; i++)
#pragma unroll
            for (int j = 0; j < 4; j++) acc[i][j] = 0ull;

#pragma unroll 1
        for (int kb = 0; kb < 48; kb++) {
            __syncthreads();
#pragma unroll
            for (int it = 0; it < 2; it++) {
                int idx = it * 256 + tid;   // 0..511
                int kk = idx >> 5;
                int cq = idx & 31;
                float4 v = *(const float4*)(W1 + (size_t)(kb * 16 + kk) * KD + jc * 128 + cq * 4);
                *(float4*)(Bs + kk * 128 + cq * 4) = v;
            }
            __syncthreads();
#pragma unroll
            for (int k4 = 0; k4 < 4; k4++) {
                float av[4][4];
#pragma unroll
                for (int i = 0; i < 4; i++) {
                    float4 t = *(const float4*)(As + (rg * 4 + i) * KD + kb * 16 + k4 * 4);
                    av[i][0] = t.x; av[i][1] = t.y; av[i][2] = t.z; av[i][3] = t.w;
                }
#pragma unroll
                for (int k = 0; k < 4; k++) {
                    const float* bp = Bs + (k4 * 4 + k) * 128 + cg * 8;
                    ulonglong2 bx = *(const ulonglong2*)bp;
                    ulonglong2 by = *(const ulonglong2*)(bp + 4);
#pragma unroll
                    for (int i = 0; i < 4; i++) {
                        unsigned long long a2;
                        asm("mov.b64 %0, {%1, %1};" : "=l"(a2) : "f"(av[i][k]));
                        asm("fma.rn.f32x2 %0, %1, %2, %0;" : "+l"(acc[i][0]) : "l"(a2), "l"(bx.x));
                        asm("fma.rn.f32x2 %0, %1, %2, %0;" : "+l"(acc[i][1]) : "l"(a2), "l"(bx.y));
                        asm("fma.rn.f32x2 %0, %1, %2, %0;" : "+l"(acc[i][2]) : "l"(a2), "l"(by.x));
                        asm("fma.rn.f32x2 %0, %1, %2, %0;" : "+l"(acc[i][3]) : "l"(a2), "l"(by.y));
                    }
                }
            }
        }
        // epilogue for this hidden chunk: relu(+b1) then fold through W2 (L2-hot)
#pragma unroll
        for (int j2 = 0; j2 < 4; j2++) {
            int c = jc * 128 + cg * 8 + j2 * 2;
            float4 w00 = __ldg((const float4*)(W2 + (size_t)c * 12));
            float4 w01 = __ldg((const float4*)(W2 + (size_t)c * 12 + 4));
            float4 w02 = __ldg((const float4*)(W2 + (size_t)c * 12 + 8));
            float4 w10 = __ldg((const float4*)(W2 + (size_t)(c + 1) * 12));
            float4 w11 = __ldg((const float4*)(W2 + (size_t)(c + 1) * 12 + 4));
            float4 w12 = __ldg((const float4*)(W2 + (size_t)(c + 1) * 12 + 8));
            float bb0 = b1s[c], bb1 = b1s[c + 1];
#pragma unroll
            for (int i = 0; i < 4; i++) {
                float h0, h1;
                asm("mov.b64 {%0, %1}, %2;" : "=f"(h0), "=f"(h1) : "l"(acc[i][j2]));
                h0 = fmaxf(h0 + bb0, 0.0f);
                h1 = fmaxf(h1 + bb1, 0.0f);
                pacc[i][0]  += h0 * w00.x + h1 * w10.x;
                pacc[i][1]  += h0 * w00.y + h1 * w10.y;
                pacc[i][2]  += h0 * w00.z + h1 * w10.z;
                pacc[i][3]  += h0 * w00.w + h1 * w10.w;
                pacc[i][4]  += h0 * w01.x + h1 * w11.x;
                pacc[i][5]  += h0 * w01.y + h1 * w11.y;
                pacc[i][6]  += h0 * w01.z + h1 * w11.z;
                pacc[i][7]  += h0 * w01.w + h1 * w11.w;
                pacc[i][8]  += h0 * w02.x + h1 * w12.x;
                pacc[i][9]  += h0 * w02.y + h1 * w12.y;
                pacc[i][10] += h0 * w02.z + h1 * w12.z;
                pacc[i][11] += h0 * w02.w + h1 * w12.w;
            }
        }
    }

    // reduce partial outs over the 16 cg lanes (xor widths stay inside 16-lane halves)
    float b2v[12];
#pragma unroll
    for (int hh = 0; hh < 12; hh++) b2v[hh] = __ldg(&b2[hh]);
#pragma unroll
    for (int i = 0; i < 4; i++) {
#pragma unroll
        for (int hh = 0; hh < 12; hh++) {
            float v = pacc[i][hh];
            v += __shfl_xor_sync(0xffffffffu, v, 8);
            v += __shfl_xor_sync(0xffffffffu, v, 4);
            v += __shfl_xor_sync(0xffffffffu, v, 2);
            v += __shfl_xor_sync(0xffffffffu, v, 1);
            if (cg == 0) out[(r0 + rg * 4 + i) * 12 + hh] = v + b2v[hh];
        }
    }
}

// --------------------------------- launch ---------------------------------
extern "C" void kernel_launch(void* const* d_in, const int* in_sizes, int n_in,
                              void* d_out, int out_size) {
    const float* patch_x = (const float*)d_in[0];
    const float* nodes_x = (const float*)d_in[1];
    const int*   batch   = (const int*)d_in[2];
    const int*   mapper  = (const int*)d_in[3];
    const float* W1      = (const float*)d_in[4];
    const float* b1      = (const float*)d_in[5];
    const float* W2      = (const float*)d_in[6];
    const float* b2      = (const float*)d_in[7];
    float*       out     = (float*)d_out;

    cudaFuncSetAttribute(k_gemm, cudaFuncAttributeMaxDynamicSharedMemorySize, SMEM_BYTES);

    k_init <<<(N_ + 255) / 256, 256>>>();
    k_count<<<(E_ + 255) / 256, 256>>>(mapper);
    k_scan <<<1, 1024>>>();
    k_fill <<<(E_ + 255) / 256, 256>>>(mapper, batch);
    k_build<<<(N_ * B_) / 8, 256>>>(patch_x, nodes_x);
    k_gemm <<<(B_ * (size_t)N_) / 64, 256, SMEM_BYTES>>>(W1, b1, W2, b2, out);
}

// round 4
// speedup vs baseline: 1.0019x; 1.0019x over previous
#include <cuda_runtime.h>

#define B_  8
#define T_  12
#define P_  1000
#define N_  20000
#define E_  60000
#define FP_ 32
#define FN_ 32
#define H_  12
#define KD  768   // IN_DIM = HID = (FP+FN)*T

// ---------------- device scratch (no allocations allowed) ----------------
__device__ int   g_cnt[N_];
__device__ int   g_cursor[N_];
__device__ int   g_offs[N_ + 1];
__device__ int   g_edge[E_];
__device__ float g_mlp[(size_t)B_ * N_ * KD];   // 160000 x 768 fp32 (491.5 MB)

// ---------------- CSR build: node -> list of patch indices ----------------
__global__ void k_init() {
    int i = blockIdx.x * blockDim.x + threadIdx.x;
    if (i < N_) g_cnt[i] = 0;
}

__global__ void k_count(const int* __restrict__ mapper) {
    int e = blockIdx.x * blockDim.x + threadIdx.x;
    if (e < E_) atomicAdd(&g_cnt[mapper[e]], 1);
}

// exclusive scan of g_cnt (N=20000) with one 1024-thread block; also zeroes cursor
__global__ void k_scan() {
    __shared__ int wsum[32];
    const int per = 20;
    int tid  = threadIdx.x;
    int base = tid * per;
    int loc[20];
    int s = 0;
#pragma unroll
    for (int i = 0; i < per; i++) {
        int idx = base + i;
        int v = (idx < N_) ? g_cnt[idx] : 0;
        loc[i] = s;
        s += v;
    }
    int lane = tid & 31, w = tid >> 5;
    int inc = s;
#pragma unroll
    for (int o = 1; o < 32; o <<= 1) {
        int t = __shfl_up_sync(0xffffffffu, inc, o);
        if (lane >= o) inc += t;
    }
    if (lane == 31) wsum[w] = inc;
    __syncthreads();
    if (w == 0) {
        int v = wsum[lane], vi = v;
#pragma unroll
        for (int o = 1; o < 32; o <<= 1) {
            int t = __shfl_up_sync(0xffffffffu, vi, o);
            if (lane >= o) vi += t;
        }
        wsum[lane] = vi - v;   // exclusive warp prefix
    }
    __syncthreads();
    int tbase = wsum[w] + (inc - s);
#pragma unroll
    for (int i = 0; i < per; i++) {
        int idx = base + i;
        if (idx <= N_) g_offs[idx] = tbase + loc[i];
    }
    for (int i = tid; i < N_; i += blockDim.x) g_cursor[i] = 0;
}

__global__ void k_fill(const int* __restrict__ mapper, const int* __restrict__ batch) {
    int e = blockIdx.x * blockDim.x + threadIdx.x;
    if (e < E_) {
        int node = mapper[e];
        int pos  = atomicAdd(&g_cursor[node], 1);
        g_edge[g_offs[node] + pos] = batch[e];
    }
}

// ------- build mlp_in: [nx transpose | segment-mean of gathered patch_x] -------
// one warp per (n, b): lane -> (tq = lane/8 in 0..3, fq = 4*(lane%8));
// each lane owns t in {tq, tq+4, tq+8}, 4 floats each.
__global__ void __launch_bounds__(256) k_build(const float* __restrict__ patch_x,
                                               const float* __restrict__ nodes_x) {
    int gw = blockIdx.x * 8 + (threadIdx.x >> 5);
    if (gw >= N_ * B_) return;
    int n = gw >> 3;
    int b = gw & 7;
    int lane = threadIdx.x & 31;
    int fq = (lane & 7) * 4;
    int tq = lane >> 3;

    float* dst = g_mlp + (size_t)(b * N_ + n) * KD;

    // first half: nodes_x (B,T,N,FN) -> cols t*32+f
#pragma unroll
    for (int j = 0; j < 3; j++) {
        int t = tq + 4 * j;
        float4 v = __ldg((const float4*)(nodes_x + ((size_t)(b * T_ + t) * N_ + n) * FN_ + fq));
        *(float4*)(dst + t * FN_ + fq) = v;
    }

    // second half: mean over this node's patches of patch_x (B,T,P,FP)
    int o0 = g_offs[n], o1 = g_offs[n + 1];
    float4 a0 = make_float4(0.f, 0.f, 0.f, 0.f), a1 = a0, a2 = a0;
    for (int e = o0; e < o1; e++) {
        int p = __ldg(&g_edge[e]);
        float4 v0 = __ldg((const float4*)(patch_x + ((size_t)(b * T_ + tq)     * P_ + p) * FP_ + fq));
        float4 v1 = __ldg((const float4*)(patch_x + ((size_t)(b * T_ + tq + 4) * P_ + p) * FP_ + fq));
        float4 v2 = __ldg((const float4*)(patch_x + ((size_t)(b * T_ + tq + 8) * P_ + p) * FP_ + fq));
        a0.x += v0.x; a0.y += v0.y; a0.z += v0.z; a0.w += v0.w;
        a1.x += v1.x; a1.y += v1.y; a1.z += v1.z; a1.w += v1.w;
        a2.x += v2.x; a2.y += v2.y; a2.z += v2.z; a2.w += v2.w;
    }
    int deg = o1 - o0;
    float inv = 1.0f / (float)(deg > 1 ? deg : 1);
    a0.x *= inv; a0.y *= inv; a0.z *= inv; a0.w *= inv;
    a1.x *= inv; a1.y *= inv; a1.z *= inv; a1.w *= inv;
    a2.x *= inv; a2.y *= inv; a2.z *= inv; a2.w *= inv;
    *(float4*)(dst + T_ * FN_ + tq * FP_ + fq)        = a0;
    *(float4*)(dst + T_ * FN_ + (tq + 4) * FP_ + fq)  = a1;
    *(float4*)(dst + T_ * FN_ + (tq + 8) * FP_ + fq)  = a2;
}

// ------------- fused GEMM: out = relu(mlp_in @ W1 + b1) @ W2 + b2 -------------
// block = 256 threads, 64-row tile. A (64x768) fully in smem.
// hidden processed in 6 chunks of 128; per-thread 4x8 microtile via fma.rn.f32x2.
#define SMEM_BYTES ((64 * KD + 16 * 128 + KD) * 4)

__global__ void __launch_bounds__(256, 1) k_gemm(const float* __restrict__ W1,
                                                 const float* __restrict__ b1,
                                                 const float* __restrict__ W2,
                                                 const float* __restrict__ b2,
                                                 float* __restrict__ out) {
    extern __shared__ float sm[];
    float* As  = sm;                  // [64][768]
    float* Bs  = sm + 64 * KD;        // [16][128]
    float* b1s = Bs + 16 * 128;       // [768]

    int tid = threadIdx.x;
    size_t r0 = (size_t)blockIdx.x * 64;
    const float* Ag = g_mlp + r0 * KD;

    // load A tile: warp = one row, 32 consecutive float4 (coalesced, conflict-free store)
#pragma unroll
    for (int it = 0; it < 48; it++) {
        int idx = it * 256 + tid;          // 0..12287
        int row = idx / 192;
        int kq  = idx - row * 192;
        float4 v = *(const float4*)(Ag + (size_t)row * KD + kq * 4);
        *(float4*)(As + row * KD + kq * 4) = v;
    }
    for (int i = tid; i < KD; i += 256) b1s[i] = b1[i];

    int rg = tid >> 4;   // 0..15: 4-row group
    int cg = tid & 15;   // 0..15: 8-col group

    float pacc[4][12];
#pragma unroll
    for (int i = 0; i < 4; i++)
#pragma unroll
        for (int hh = 0; hh < 12; hh++) pacc[i][hh] = 0.f;

#pragma unroll 1
    for (int jc = 0; jc < 6; jc++) {
        unsigned long long acc[4][4];   // 4 rows x 4 col-pairs (f32x2)
#pragma unroll
        for (int i = 0; i < 4; i++)
#pragma unroll
            for (int j = 0; j < 4; j++) acc[i][j] = 0ull;

#pragma unroll 1
        for (int kb = 0; kb < 48; kb++) {
            __syncthreads();
#pragma unroll
            for (int it = 0; it < 2; it++) {
                int idx = it * 256 + tid;   // 0..511
                int kk = idx >> 5;
                int cq = idx & 31;
                float4 v = *(const float4*)(W1 + (size_t)(kb * 16 + kk) * KD + jc * 128 + cq * 4);
                *(float4*)(Bs + kk * 128 + cq * 4) = v;
            }
            __syncthreads();
#pragma unroll
            for (int k4 = 0; k4 < 4; k4++) {
                float av[4][4];
#pragma unroll
                for (int i = 0; i < 4; i++) {
                    float4 t = *(const float4*)(As + (rg * 4 + i) * KD + kb * 16 + k4 * 4);
                    av[i][0] = t.x; av[i][1] = t.y; av[i][2] = t.z; av[i][3] = t.w;
                }
#pragma unroll
                for (int k = 0; k < 4; k++) {
                    const float* bp = Bs + (k4 * 4 + k) * 128 + cg * 8;
                    ulonglong2 bx = *(const ulonglong2*)bp;
                    ulonglong2 by = *(const ulonglong2*)(bp + 4);
#pragma unroll
                    for (int i = 0; i < 4; i++) {
                        unsigned long long a2;
                        asm("mov.b64 %0, {%1, %1};" : "=l"(a2) : "f"(av[i][k]));
                        asm("fma.rn.f32x2 %0, %1, %2, %0;" : "+l"(acc[i][0]) : "l"(a2), "l"(bx.x));
                        asm("fma.rn.f32x2 %0, %1, %2, %0;" : "+l"(acc[i][1]) : "l"(a2), "l"(bx.y));
                        asm("fma.rn.f32x2 %0, %1, %2, %0;" : "+l"(acc[i][2]) : "l"(a2), "l"(by.x));
                        asm("fma.rn.f32x2 %0, %1, %2, %0;" : "+l"(acc[i][3]) : "l"(a2), "l"(by.y));
                    }
                }
            }
        }
        // epilogue for this hidden chunk: relu(+b1) then fold through W2 (L2-hot)
#pragma unroll
        for (int j2 = 0; j2 < 4; j2++) {
            int c = jc * 128 + cg * 8 + j2 * 2;
            float4 w00 = __ldg((const float4*)(W2 + (size_t)c * 12));
            float4 w01 = __ldg((const float4*)(W2 + (size_t)c * 12 + 4));
            float4 w02 = __ldg((const float4*)(W2 + (size_t)c * 12 + 8));
            float4 w10 = __ldg((const float4*)(W2 + (size_t)(c + 1) * 12));
            float4 w11 = __ldg((const float4*)(W2 + (size_t)(c + 1) * 12 + 4));
            float4 w12 = __ldg((const float4*)(W2 + (size_t)(c + 1) * 12 + 8));
            float bb0 = b1s[c], bb1 = b1s[c + 1];
#pragma unroll
            for (int i = 0; i < 4; i++) {
                float h0, h1;
                asm("mov.b64 {%0, %1}, %2;" : "=f"(h0), "=f"(h1) : "l"(acc[i][j2]));
                h0 = fmaxf(h0 + bb0, 0.0f);
                h1 = fmaxf(h1 + bb1, 0.0f);
                pacc[i][0]  += h0 * w00.x + h1 * w10.x;
                pacc[i][1]  += h0 * w00.y + h1 * w10.y;
                pacc[i][2]  += h0 * w00.z + h1 * w10.z;
                pacc[i][3]  += h0 * w00.w + h1 * w10.w;
                pacc[i][4]  += h0 * w01.x + h1 * w11.x;
                pacc[i][5]  += h0 * w01.y + h1 * w11.y;
                pacc[i][6]  += h0 * w01.z + h1 * w11.z;
                pacc[i][7]  += h0 * w01.w + h1 * w11.w;
                pacc[i][8]  += h0 * w02.x + h1 * w12.x;
                pacc[i][9]  += h0 * w02.y + h1 * w12.y;
                pacc[i][10] += h0 * w02.z + h1 * w12.z;
                pacc[i][11] += h0 * w02.w + h1 * w12.w;
            }
        }
    }

    // reduce partial outs over the 16 cg lanes (xor widths stay inside 16-lane halves)
    float b2v[12];
#pragma unroll
    for (int hh = 0; hh < 12; hh++) b2v[hh] = __ldg(&b2[hh]);
#pragma unroll
    for (int i = 0; i < 4; i++) {
#pragma unroll
        for (int hh = 0; hh < 12; hh++) {
            float v = pacc[i][hh];
            v += __shfl_xor_sync(0xffffffffu, v, 8);
            v += __shfl_xor_sync(0xffffffffu, v, 4);
            v += __shfl_xor_sync(0xffffffffu, v, 2);
            v += __shfl_xor_sync(0xffffffffu, v, 1);
            if (cg == 0) out[(r0 + rg * 4 + i) * 12 + hh] = v + b2v[hh];
        }
    }
}

// --------------------------------- launch ---------------------------------
extern "C" void kernel_launch(void* const* d_in, const int* in_sizes, int n_in,
                              void* d_out, int out_size) {
    const float* patch_x = (const float*)d_in[0];
    const float* nodes_x = (const float*)d_in[1];
    const int*   batch   = (const int*)d_in[2];
    const int*   mapper  = (const int*)d_in[3];
    const float* W1      = (const float*)d_in[4];
    const float* b1      = (const float*)d_in[5];
    const float* W2      = (const float*)d_in[6];
    const float* b2      = (const float*)d_in[7];
    float*       out     = (float*)d_out;

    cudaFuncSetAttribute(k_gemm, cudaFuncAttributeMaxDynamicSharedMemorySize, SMEM_BYTES);

    k_init <<<(N_ + 255) / 256, 256>>>();
    k_count<<<(E_ + 255) / 256, 256>>>(mapper);
    k_scan <<<1, 1024>>>();
    k_fill <<<(E_ + 255) / 256, 256>>>(mapper, batch);
    k_build<<<(N_ * B_) / 8, 256>>>(patch_x, nodes_x);
    k_gemm <<<(B_ * (size_t)N_) / 64, 256, SMEM_BYTES>>>(W1, b1, W2, b2, out);
}